// round 1
// baseline (speedup 1.0000x reference)
#include <cuda_runtime.h>
#include <math.h>

// Problem constants (fixed shapes)
#define T_SEQ 2048
#define NB    2
#define C_DIM 1024
#define H_NUM 16
#define DH    64
#define M_ROWS (T_SEQ * NB)   // 4096
#define WIN   128
#define SCALE 0.125f          // 1/sqrt(64)

// Scratch: projected Q/K/V in (N, H, T, Dh) layout + attention output in (M, C)
__device__ float g_q[NB * H_NUM * T_SEQ * DH];
__device__ float g_k[NB * H_NUM * T_SEQ * DH];
__device__ float g_v[NB * H_NUM * T_SEQ * DH];
__device__ float g_y[M_ROWS * C_DIM];

// ---------------------------------------------------------------------------
// SGEMM: out = X @ W^T + bias.  X: (M, K) row-major, W: (Nout, K) row-major.
// mode 0/1/2: scatter to g_q/g_k/g_v in (n,h,t,dh) layout.
// mode 3:     X is g_y, write plain row-major (M, C) to outp (d_out).
// Tile: 128x128x8, 256 threads, 8x8 per thread.
// ---------------------------------------------------------------------------
__global__ __launch_bounds__(256) void sgemm_xwt(
    const float* __restrict__ X, const float* __restrict__ W,
    const float* __restrict__ bias, float* __restrict__ outp, int mode)
{
    __shared__ float As[8][128];
    __shared__ float Bs[8][128];

    const int K = C_DIM;
    const int m0 = blockIdx.x * 128;
    const int o0 = blockIdx.y * 128;
    const int tid = threadIdx.x;
    const int tx = tid & 15;
    const int ty = tid >> 4;

    const float* Xe = (mode == 3) ? g_y : X;

    float acc[8][8];
    #pragma unroll
    for (int i = 0; i < 8; i++)
        #pragma unroll
        for (int j = 0; j < 8; j++) acc[i][j] = 0.0f;

    const int lrow = tid >> 1;        // 0..127
    const int lk   = (tid & 1) * 4;   // 0 or 4
    const float* Aptr = Xe + (size_t)(m0 + lrow) * K + lk;
    const float* Bptr = W  + (size_t)(o0 + lrow) * K + lk;

    for (int k0 = 0; k0 < K; k0 += 8) {
        float4 a4 = *(const float4*)(Aptr + k0);
        float4 b4 = *(const float4*)(Bptr + k0);
        __syncthreads();   // previous iteration's compute done reading smem
        As[lk + 0][lrow] = a4.x; As[lk + 1][lrow] = a4.y;
        As[lk + 2][lrow] = a4.z; As[lk + 3][lrow] = a4.w;
        Bs[lk + 0][lrow] = b4.x; Bs[lk + 1][lrow] = b4.y;
        Bs[lk + 2][lrow] = b4.z; Bs[lk + 3][lrow] = b4.w;
        __syncthreads();

        #pragma unroll
        for (int kk = 0; kk < 8; kk++) {
            float4 aA = *(const float4*)&As[kk][ty * 4];
            float4 aB = *(const float4*)&As[kk][64 + ty * 4];
            float4 bA = *(const float4*)&Bs[kk][tx * 4];
            float4 bB = *(const float4*)&Bs[kk][64 + tx * 4];
            float ra[8] = {aA.x, aA.y, aA.z, aA.w, aB.x, aB.y, aB.z, aB.w};
            float rb[8] = {bA.x, bA.y, bA.z, bA.w, bB.x, bB.y, bB.z, bB.w};
            #pragma unroll
            for (int i = 0; i < 8; i++)
                #pragma unroll
                for (int j = 0; j < 8; j++)
                    acc[i][j] += ra[i] * rb[j];
        }
    }

    // Epilogue
    #pragma unroll
    for (int i = 0; i < 8; i++) {
        int m = m0 + ((i < 4) ? (ty * 4 + i) : (64 + ty * 4 + i - 4));
        #pragma unroll
        for (int j = 0; j < 8; j++) {
            int o = o0 + ((j < 4) ? (tx * 4 + j) : (64 + tx * 4 + j - 4));
            float val = acc[i][j] + bias[o];
            if (mode <= 2) {
                int t = m >> 1, n = m & 1;
                int h = o >> 6, dh = o & 63;
                float* dst = (mode == 0) ? g_q : (mode == 1) ? g_k : g_v;
                dst[(((size_t)(n * H_NUM + h)) * T_SEQ + t) * DH + dh] = val;
            } else {
                outp[(size_t)m * C_DIM + o] = val;
            }
        }
    }
}

// ---------------------------------------------------------------------------
// Flash attention with banded-local + prefix mask, block-level sparsity skip.
// grid: (T/BQ, H, N), 256 threads. BQ=64 queries, BK=32 keys per step.
// Thread (ty,tx) (16x16): owns S rows ty*4..+3, S cols tx*2..+1,
// O tile rows ty*4..+3 x cols tx*4..+3.
// ---------------------------------------------------------------------------
#define BQ 64
#define BK 32
#define QPAD 68
#define PPAD 36

__global__ __launch_bounds__(256) void attn_kernel(const int* __restrict__ key_length)
{
    __shared__ float Qs[BQ][QPAD];
    __shared__ float Ks[BK][QPAD];
    __shared__ float Vs[BK][QPAD];
    __shared__ float Ps[BQ][PPAD];

    const int i0 = blockIdx.x * BQ;
    const int h  = blockIdx.y;
    const int n  = blockIdx.z;
    const int tid = threadIdx.x;
    const int tx = tid & 15;
    const int ty = tid >> 4;
    const int ri0 = ty * 4;
    const int cj0 = tx * 2;
    const int keylen = key_length[n];

    const float* Qg = g_q + ((size_t)(n * H_NUM + h)) * T_SEQ * DH;
    const float* Kg = g_k + ((size_t)(n * H_NUM + h)) * T_SEQ * DH;
    const float* Vg = g_v + ((size_t)(n * H_NUM + h)) * T_SEQ * DH;

    // Load + scale Q tile (64 x 64)
    {
        int r = tid >> 2;
        int c = (tid & 3) * 16;
        #pragma unroll
        for (int u = 0; u < 4; u++) {
            float4 v4 = *(const float4*)(Qg + (size_t)(i0 + r) * DH + c + u * 4);
            v4.x *= SCALE; v4.y *= SCALE; v4.z *= SCALE; v4.w *= SCALE;
            *(float4*)&Qs[r][c + u * 4] = v4;
        }
    }

    float m_i[4], l_i[4], oacc[4][4];
    #pragma unroll
    for (int a = 0; a < 4; a++) {
        m_i[a] = -1e30f;
        l_i[a] = 0.0f;
        #pragma unroll
        for (int b = 0; b < 4; b++) oacc[a][b] = 0.0f;
    }
    __syncthreads();

    for (int j0 = 0; j0 < T_SEQ; j0 += BK) {
        // Block needed iff it intersects the prefix region or the local band.
        bool needed = (j0 < keylen) ||
                      ((j0 + BK - 1 >= i0 - WIN) && (j0 <= i0 + BQ - 1 + WIN));
        if (!needed) continue;

        // Load K,V tiles (32 x 64 each)
        {
            int r = tid >> 3;          // 0..31
            int c = (tid & 7) * 8;     // 0..56
            *(float4*)&Ks[r][c]     = *(const float4*)(Kg + (size_t)(j0 + r) * DH + c);
            *(float4*)&Ks[r][c + 4] = *(const float4*)(Kg + (size_t)(j0 + r) * DH + c + 4);
            *(float4*)&Vs[r][c]     = *(const float4*)(Vg + (size_t)(j0 + r) * DH + c);
            *(float4*)&Vs[r][c + 4] = *(const float4*)(Vg + (size_t)(j0 + r) * DH + c + 4);
        }
        __syncthreads();

        // S = (Q*scale) @ K^T  for this tile
        float s[4][2];
        #pragma unroll
        for (int a = 0; a < 4; a++) { s[a][0] = 0.0f; s[a][1] = 0.0f; }
        #pragma unroll
        for (int k = 0; k < DH; k += 4) {
            float4 k0 = *(const float4*)&Ks[cj0][k];
            float4 k1 = *(const float4*)&Ks[cj0 + 1][k];
            #pragma unroll
            for (int a = 0; a < 4; a++) {
                float4 q4 = *(const float4*)&Qs[ri0 + a][k];
                s[a][0] += q4.x * k0.x + q4.y * k0.y + q4.z * k0.z + q4.w * k0.w;
                s[a][1] += q4.x * k1.x + q4.y * k1.y + q4.z * k1.z + q4.w * k1.w;
            }
        }

        // Mask
        #pragma unroll
        for (int a = 0; a < 4; a++) {
            int ig = i0 + ri0 + a;
            #pragma unroll
            for (int cc = 0; cc < 2; cc++) {
                int jg = j0 + cj0 + cc;
                int d = ig - jg;
                bool allowed = (jg < keylen) || (d <= WIN && d >= -WIN);
                if (!allowed) s[a][cc] = -1e30f;
            }
        }

        // Online softmax update
        #pragma unroll
        for (int a = 0; a < 4; a++) {
            float mb = fmaxf(s[a][0], s[a][1]);
            #pragma unroll
            for (int off = 8; off; off >>= 1)
                mb = fmaxf(mb, __shfl_xor_sync(0xffffffffu, mb, off));
            float mn = fmaxf(m_i[a], mb);
            float corr = __expf(m_i[a] - mn);
            float p0 = (s[a][0] < -1e29f) ? 0.0f : __expf(s[a][0] - mn);
            float p1 = (s[a][1] < -1e29f) ? 0.0f : __expf(s[a][1] - mn);
            float ls = p0 + p1;
            #pragma unroll
            for (int off = 8; off; off >>= 1)
                ls += __shfl_xor_sync(0xffffffffu, ls, off);
            l_i[a] = l_i[a] * corr + ls;
            m_i[a] = mn;
            #pragma unroll
            for (int b = 0; b < 4; b++) oacc[a][b] *= corr;
            Ps[ri0 + a][cj0]     = p0;
            Ps[ri0 + a][cj0 + 1] = p1;
        }
        __syncthreads();

        // O += P @ V
        #pragma unroll 4
        for (int j = 0; j < BK; j++) {
            float4 v4 = *(const float4*)&Vs[j][tx * 4];
            #pragma unroll
            for (int a = 0; a < 4; a++) {
                float p = Ps[ri0 + a][j];
                oacc[a][0] += p * v4.x;
                oacc[a][1] += p * v4.y;
                oacc[a][2] += p * v4.z;
                oacc[a][3] += p * v4.w;
            }
        }
        __syncthreads();
    }

    // Normalize and write to g_y in (t, n, c) layout
    #pragma unroll
    for (int a = 0; a < 4; a++) {
        float inv = 1.0f / l_i[a];
        int ig = i0 + ri0 + a;
        float4 o4;
        o4.x = oacc[a][0] * inv;
        o4.y = oacc[a][1] * inv;
        o4.z = oacc[a][2] * inv;
        o4.w = oacc[a][3] * inv;
        *(float4*)&g_y[((size_t)ig * NB + n) * C_DIM + h * DH + tx * 4] = o4;
    }
}

// ---------------------------------------------------------------------------
extern "C" void kernel_launch(void* const* d_in, const int* in_sizes, int n_in,
                              void* d_out, int out_size)
{
    const float* q  = (const float*)d_in[0];
    const float* k  = (const float*)d_in[1];
    const float* v  = (const float*)d_in[2];
    const float* Wq = (const float*)d_in[3];
    const float* bq = (const float*)d_in[4];
    const float* Wk = (const float*)d_in[5];
    const float* bk = (const float*)d_in[6];
    const float* Wv = (const float*)d_in[7];
    const float* bv = (const float*)d_in[8];
    const float* Wo = (const float*)d_in[9];
    const float* bo = (const float*)d_in[10];
    const int* keylen = (const int*)d_in[11];

    dim3 gg(M_ROWS / 128, C_DIM / 128);
    dim3 gb(256);

    sgemm_xwt<<<gg, gb>>>(q, Wq, bq, nullptr, 0);
    sgemm_xwt<<<gg, gb>>>(k, Wk, bk, nullptr, 1);
    sgemm_xwt<<<gg, gb>>>(v, Wv, bv, nullptr, 2);

    attn_kernel<<<dim3(T_SEQ / BQ, H_NUM, NB), 256>>>(keylen);

    sgemm_xwt<<<gg, gb>>>(nullptr, Wo, bo, (float*)d_out, 3);
}

// round 3
// speedup vs baseline: 1.3675x; 1.3675x over previous
#include <cuda_runtime.h>
#include <math.h>

// Problem constants (fixed shapes)
#define T_SEQ 2048
#define NB    2
#define C_DIM 1024
#define H_NUM 16
#define DH    64
#define M_ROWS (T_SEQ * NB)   // 4096
#define WIN   128
#define SCALE 0.125f          // 1/sqrt(64)

// Scratch: projected Q/K/V in (N, H, T, Dh) layout + attention output in (M, C)
__device__ float g_q[NB * H_NUM * T_SEQ * DH];
__device__ float g_k[NB * H_NUM * T_SEQ * DH];
__device__ float g_v[NB * H_NUM * T_SEQ * DH];
__device__ float g_y[M_ROWS * C_DIM];

__device__ __forceinline__ unsigned f2tf32(float x) {
    unsigned y;
    asm("cvt.rna.tf32.f32 %0, %1;" : "=r"(y) : "f"(x));
    return y;
}

// ---------------------------------------------------------------------------
// TF32 tensor-core GEMM: out = X @ W^T + bias.
// X: (M, K) row-major, W: (Nout, K) row-major — both K-contiguous.
// Block tile 128x128, K staged 32; 8 warps as 2(M) x 4(N), warp tile 64x32.
// mma.sync.m16n8k8 tf32, fp32 accumulate.
// mode 0/1/2: scatter to g_q/g_k/g_v in (n,h,t,dh) layout.  mode 3: g_y -> outp.
// ---------------------------------------------------------------------------
#define SMA 132   // padded m/n stride for k-major smem tiles

__global__ __launch_bounds__(256) void mma_gemm(
    const float* __restrict__ X, const float* __restrict__ W,
    const float* __restrict__ bias, float* __restrict__ outp, int mode)
{
    __shared__ unsigned As[32][SMA];   // As[k][m], tf32 bits
    __shared__ unsigned Bs[32][SMA];   // Bs[k][n], tf32 bits

    const int K = C_DIM;
    const int m0 = blockIdx.x * 128;
    const int o0 = blockIdx.y * 128;
    const int tid = threadIdx.x;
    const int lane = tid & 31;
    const int wid = tid >> 5;
    const int warp_m = wid & 1;        // 0,1 -> 64 rows each
    const int warp_n = wid >> 1;       // 0..3 -> 32 cols each
    const int lr = lane >> 2;          // 0..7
    const int lc = lane & 3;           // 0..3

    const float* Xe = (mode == 3) ? g_y : X;

    // Global staging: thread covers row r, k = kbase + {0..15} within stage
    const int r = tid >> 1;            // 0..127
    const int kbase = (tid & 1) * 16;  // 0 or 16
    const float* Aptr = Xe + (size_t)(m0 + r) * K + kbase;
    const float* Bptr = W  + (size_t)(o0 + r) * K + kbase;

    float c[4][4][4];
    #pragma unroll
    for (int t = 0; t < 4; t++)
        #pragma unroll
        for (int u = 0; u < 4; u++)
            #pragma unroll
            for (int e = 0; e < 4; e++) c[t][u][e] = 0.0f;

    float4 ra[4], rb[4];
    #pragma unroll
    for (int u = 0; u < 4; u++) {
        ra[u] = *(const float4*)(Aptr + u * 4);
        rb[u] = *(const float4*)(Bptr + u * 4);
    }

    for (int k0 = 0; k0 < K; k0 += 32) {
        __syncthreads();  // previous stage's MMA reads done
        #pragma unroll
        for (int u = 0; u < 4; u++) {
            As[kbase + u * 4 + 0][r] = f2tf32(ra[u].x);
            As[kbase + u * 4 + 1][r] = f2tf32(ra[u].y);
            As[kbase + u * 4 + 2][r] = f2tf32(ra[u].z);
            As[kbase + u * 4 + 3][r] = f2tf32(ra[u].w);
            Bs[kbase + u * 4 + 0][r] = f2tf32(rb[u].x);
            Bs[kbase + u * 4 + 1][r] = f2tf32(rb[u].y);
            Bs[kbase + u * 4 + 2][r] = f2tf32(rb[u].z);
            Bs[kbase + u * 4 + 3][r] = f2tf32(rb[u].w);
        }
        __syncthreads();

        // Prefetch next stage (LDGs overlap MMA work below)
        if (k0 + 32 < K) {
            #pragma unroll
            for (int u = 0; u < 4; u++) {
                ra[u] = *(const float4*)(Aptr + k0 + 32 + u * 4);
                rb[u] = *(const float4*)(Bptr + k0 + 32 + u * 4);
            }
        }

        #pragma unroll
        for (int kk = 0; kk < 32; kk += 8) {
            unsigned af[4][4], bf[4][2];
            #pragma unroll
            for (int t = 0; t < 4; t++) {
                int mb = warp_m * 64 + t * 16 + lr;
                af[t][0] = As[kk + lc][mb];
                af[t][1] = As[kk + lc][mb + 8];
                af[t][2] = As[kk + lc + 4][mb];
                af[t][3] = As[kk + lc + 4][mb + 8];
            }
            #pragma unroll
            for (int u = 0; u < 4; u++) {
                int nb = warp_n * 32 + u * 8 + lr;
                bf[u][0] = Bs[kk + lc][nb];
                bf[u][1] = Bs[kk + lc + 4][nb];
            }
            #pragma unroll
            for (int t = 0; t < 4; t++)
                #pragma unroll
                for (int u = 0; u < 4; u++) {
                    asm volatile(
                        "mma.sync.aligned.m16n8k8.row.col.f32.tf32.tf32.f32 "
                        "{%0,%1,%2,%3}, {%4,%5,%6,%7}, {%8,%9}, {%0,%1,%2,%3};"
                        : "+f"(c[t][u][0]), "+f"(c[t][u][1]),
                          "+f"(c[t][u][2]), "+f"(c[t][u][3])
                        : "r"(af[t][0]), "r"(af[t][1]), "r"(af[t][2]), "r"(af[t][3]),
                          "r"(bf[u][0]), "r"(bf[u][1]));
                }
        }
    }

    // Epilogue: c[t][u]: rows {lr, lr+8}, cols {2*lc, 2*lc+1}
    #pragma unroll
    for (int t = 0; t < 4; t++) {
        int row0 = m0 + warp_m * 64 + t * 16 + lr;
        #pragma unroll
        for (int u = 0; u < 4; u++) {
            int col0 = o0 + warp_n * 32 + u * 8 + lc * 2;
            #pragma unroll
            for (int e = 0; e < 4; e++) {
                int m = row0 + (e >> 1) * 8;
                int o = col0 + (e & 1);
                float val = c[t][u][e] + bias[o];
                if (mode <= 2) {
                    int tt = m >> 1, n = m & 1;
                    int h = o >> 6, dh = o & 63;
                    float* dst = (mode == 0) ? g_q : (mode == 1) ? g_k : g_v;
                    dst[(((size_t)(n * H_NUM + h)) * T_SEQ + tt) * DH + dh] = val;
                } else {
                    outp[(size_t)m * C_DIM + o] = val;
                }
            }
        }
    }
}

// ---------------------------------------------------------------------------
// Flash attention with banded-local + prefix mask, block-level sparsity skip.
// ---------------------------------------------------------------------------
#define BQ 64
#define BK 32
#define QPAD 68
#define PPAD 36

__global__ __launch_bounds__(256) void attn_kernel(const int* __restrict__ key_length)
{
    __shared__ float Qs[BQ][QPAD];
    __shared__ float Ks[BK][QPAD];
    __shared__ float Vs[BK][QPAD];
    __shared__ float Ps[BQ][PPAD];

    const int i0 = blockIdx.x * BQ;
    const int h  = blockIdx.y;
    const int n  = blockIdx.z;
    const int tid = threadIdx.x;
    const int tx = tid & 15;
    const int ty = tid >> 4;
    const int ri0 = ty * 4;
    const int cj0 = tx * 2;
    const int keylen = key_length[n];

    const float* Qg = g_q + ((size_t)(n * H_NUM + h)) * T_SEQ * DH;
    const float* Kg = g_k + ((size_t)(n * H_NUM + h)) * T_SEQ * DH;
    const float* Vg = g_v + ((size_t)(n * H_NUM + h)) * T_SEQ * DH;

    {
        int r = tid >> 2;
        int c = (tid & 3) * 16;
        #pragma unroll
        for (int u = 0; u < 4; u++) {
            float4 v4 = *(const float4*)(Qg + (size_t)(i0 + r) * DH + c + u * 4);
            v4.x *= SCALE; v4.y *= SCALE; v4.z *= SCALE; v4.w *= SCALE;
            *(float4*)&Qs[r][c + u * 4] = v4;
        }
    }

    float m_i[4], l_i[4], oacc[4][4];
    #pragma unroll
    for (int a = 0; a < 4; a++) {
        m_i[a] = -1e30f;
        l_i[a] = 0.0f;
        #pragma unroll
        for (int b = 0; b < 4; b++) oacc[a][b] = 0.0f;
    }
    __syncthreads();

    for (int j0 = 0; j0 < T_SEQ; j0 += BK) {
        bool needed = (j0 < keylen) ||
                      ((j0 + BK - 1 >= i0 - WIN) && (j0 <= i0 + BQ - 1 + WIN));
        if (!needed) continue;

        {
            int r = tid >> 3;
            int c = (tid & 7) * 8;
            *(float4*)&Ks[r][c]     = *(const float4*)(Kg + (size_t)(j0 + r) * DH + c);
            *(float4*)&Ks[r][c + 4] = *(const float4*)(Kg + (size_t)(j0 + r) * DH + c + 4);
            *(float4*)&Vs[r][c]     = *(const float4*)(Vg + (size_t)(j0 + r) * DH + c);
            *(float4*)&Vs[r][c + 4] = *(const float4*)(Vg + (size_t)(j0 + r) * DH + c + 4);
        }
        __syncthreads();

        float s[4][2];
        #pragma unroll
        for (int a = 0; a < 4; a++) { s[a][0] = 0.0f; s[a][1] = 0.0f; }
        #pragma unroll
        for (int k = 0; k < DH; k += 4) {
            float4 k0 = *(const float4*)&Ks[cj0][k];
            float4 k1 = *(const float4*)&Ks[cj0 + 1][k];
            #pragma unroll
            for (int a = 0; a < 4; a++) {
                float4 q4 = *(const float4*)&Qs[ri0 + a][k];
                s[a][0] += q4.x * k0.x + q4.y * k0.y + q4.z * k0.z + q4.w * k0.w;
                s[a][1] += q4.x * k1.x + q4.y * k1.y + q4.z * k1.z + q4.w * k1.w;
            }
        }

        #pragma unroll
        for (int a = 0; a < 4; a++) {
            int ig = i0 + ri0 + a;
            #pragma unroll
            for (int cc = 0; cc < 2; cc++) {
                int jg = j0 + cj0 + cc;
                int d = ig - jg;
                bool allowed = (jg < keylen) || (d <= WIN && d >= -WIN);
                if (!allowed) s[a][cc] = -1e30f;
            }
        }

        #pragma unroll
        for (int a = 0; a < 4; a++) {
            float mb = fmaxf(s[a][0], s[a][1]);
            #pragma unroll
            for (int off = 8; off; off >>= 1)
                mb = fmaxf(mb, __shfl_xor_sync(0xffffffffu, mb, off));
            float mn = fmaxf(m_i[a], mb);
            float corr = __expf(m_i[a] - mn);
            float p0 = (s[a][0] < -1e29f) ? 0.0f : __expf(s[a][0] - mn);
            float p1 = (s[a][1] < -1e29f) ? 0.0f : __expf(s[a][1] - mn);
            float ls = p0 + p1;
            #pragma unroll
            for (int off = 8; off; off >>= 1)
                ls += __shfl_xor_sync(0xffffffffu, ls, off);
            l_i[a] = l_i[a] * corr + ls;
            m_i[a] = mn;
            #pragma unroll
            for (int b = 0; b < 4; b++) oacc[a][b] *= corr;
            Ps[ri0 + a][cj0]     = p0;
            Ps[ri0 + a][cj0 + 1] = p1;
        }
        __syncthreads();

        #pragma unroll 4
        for (int j = 0; j < BK; j++) {
            float4 v4 = *(const float4*)&Vs[j][tx * 4];
            #pragma unroll
            for (int a = 0; a < 4; a++) {
                float p = Ps[ri0 + a][j];
                oacc[a][0] += p * v4.x;
                oacc[a][1] += p * v4.y;
                oacc[a][2] += p * v4.z;
                oacc[a][3] += p * v4.w;
            }
        }
        __syncthreads();
    }

    #pragma unroll
    for (int a = 0; a < 4; a++) {
        float inv = 1.0f / l_i[a];
        int ig = i0 + ri0 + a;
        float4 o4;
        o4.x = oacc[a][0] * inv;
        o4.y = oacc[a][1] * inv;
        o4.z = oacc[a][2] * inv;
        o4.w = oacc[a][3] * inv;
        *(float4*)&g_y[((size_t)ig * NB + n) * C_DIM + h * DH + tx * 4] = o4;
    }
}

// ---------------------------------------------------------------------------
extern "C" void kernel_launch(void* const* d_in, const int* in_sizes, int n_in,
                              void* d_out, int out_size)
{
    const float* q  = (const float*)d_in[0];
    const float* k  = (const float*)d_in[1];
    const float* v  = (const float*)d_in[2];
    const float* Wq = (const float*)d_in[3];
    const float* bq = (const float*)d_in[4];
    const float* Wk = (const float*)d_in[5];
    const float* bk = (const float*)d_in[6];
    const float* Wv = (const float*)d_in[7];
    const float* bv = (const float*)d_in[8];
    const float* Wo = (const float*)d_in[9];
    const float* bo = (const float*)d_in[10];
    const int* keylen = (const int*)d_in[11];

    dim3 gg(M_ROWS / 128, C_DIM / 128);

    mma_gemm<<<gg, 256>>>(q, Wq, bq, nullptr, 0);
    mma_gemm<<<gg, 256>>>(k, Wk, bk, nullptr, 1);
    mma_gemm<<<gg, 256>>>(v, Wv, bv, nullptr, 2);

    attn_kernel<<<dim3(T_SEQ / BQ, H_NUM, NB), 256>>>(keylen);

    mma_gemm<<<gg, 256>>>(nullptr, Wo, bo, (float*)d_out, 3);
}

// round 5
// speedup vs baseline: 1.8723x; 1.3692x over previous
#include <cuda_runtime.h>
#include <math.h>

// Problem constants (fixed shapes)
#define T_SEQ 2048
#define NB    2
#define C_DIM 1024
#define H_NUM 16
#define DH    64
#define M_ROWS (T_SEQ * NB)   // 4096
#define WIN   128
#define SCALE 0.125f          // 1/sqrt(64)

// Scratch: projected Q/K/V in (N, H, T, Dh) layout + attention output in (M, C)
__device__ float g_q[NB * H_NUM * T_SEQ * DH];
__device__ float g_k[NB * H_NUM * T_SEQ * DH];
__device__ float g_v[NB * H_NUM * T_SEQ * DH];
__device__ float g_y[M_ROWS * C_DIM];

__device__ __forceinline__ unsigned f2tf32(float x) {
    unsigned y;
    asm("cvt.rna.tf32.f32 %0, %1;" : "=r"(y) : "f"(x));
    return y;
}

__device__ __forceinline__ void mma_tf32(float* c, const unsigned* a,
                                         unsigned b0, unsigned b1) {
    asm volatile(
        "mma.sync.aligned.m16n8k8.row.col.f32.tf32.tf32.f32 "
        "{%0,%1,%2,%3}, {%4,%5,%6,%7}, {%8,%9}, {%0,%1,%2,%3};"
        : "+f"(c[0]), "+f"(c[1]), "+f"(c[2]), "+f"(c[3])
        : "r"(a[0]), "r"(a[1]), "r"(a[2]), "r"(a[3]), "r"(b0), "r"(b1));
}

// ---------------------------------------------------------------------------
// TF32 tensor-core GEMM: out = X @ W^T + bias.   (measured-good from round 3)
// ---------------------------------------------------------------------------
#define SMA 132

__global__ __launch_bounds__(256) void mma_gemm(
    const float* __restrict__ X, const float* __restrict__ W,
    const float* __restrict__ bias, float* __restrict__ outp, int mode)
{
    __shared__ unsigned As[32][SMA];   // As[k][m], tf32 bits
    __shared__ unsigned Bs[32][SMA];   // Bs[k][n], tf32 bits

    const int K = C_DIM;
    const int m0 = blockIdx.x * 128;
    const int o0 = blockIdx.y * 128;
    const int tid = threadIdx.x;
    const int lane = tid & 31;
    const int wid = tid >> 5;
    const int warp_m = wid & 1;
    const int warp_n = wid >> 1;
    const int lr = lane >> 2;
    const int lc = lane & 3;

    const float* Xe = (mode == 3) ? g_y : X;

    const int r = tid >> 1;
    const int kbase = (tid & 1) * 16;
    const float* Aptr = Xe + (size_t)(m0 + r) * K + kbase;
    const float* Bptr = W  + (size_t)(o0 + r) * K + kbase;

    float c[4][4][4];
    #pragma unroll
    for (int t = 0; t < 4; t++)
        #pragma unroll
        for (int u = 0; u < 4; u++)
            #pragma unroll
            for (int e = 0; e < 4; e++) c[t][u][e] = 0.0f;

    float4 ra[4], rb[4];
    #pragma unroll
    for (int u = 0; u < 4; u++) {
        ra[u] = *(const float4*)(Aptr + u * 4);
        rb[u] = *(const float4*)(Bptr + u * 4);
    }

    for (int k0 = 0; k0 < K; k0 += 32) {
        __syncthreads();
        #pragma unroll
        for (int u = 0; u < 4; u++) {
            As[kbase + u * 4 + 0][r] = f2tf32(ra[u].x);
            As[kbase + u * 4 + 1][r] = f2tf32(ra[u].y);
            As[kbase + u * 4 + 2][r] = f2tf32(ra[u].z);
            As[kbase + u * 4 + 3][r] = f2tf32(ra[u].w);
            Bs[kbase + u * 4 + 0][r] = f2tf32(rb[u].x);
            Bs[kbase + u * 4 + 1][r] = f2tf32(rb[u].y);
            Bs[kbase + u * 4 + 2][r] = f2tf32(rb[u].z);
            Bs[kbase + u * 4 + 3][r] = f2tf32(rb[u].w);
        }
        __syncthreads();

        if (k0 + 32 < K) {
            #pragma unroll
            for (int u = 0; u < 4; u++) {
                ra[u] = *(const float4*)(Aptr + k0 + 32 + u * 4);
                rb[u] = *(const float4*)(Bptr + k0 + 32 + u * 4);
            }
        }

        #pragma unroll
        for (int kk = 0; kk < 32; kk += 8) {
            unsigned af[4][4], bf[4][2];
            #pragma unroll
            for (int t = 0; t < 4; t++) {
                int mb = warp_m * 64 + t * 16 + lr;
                af[t][0] = As[kk + lc][mb];
                af[t][1] = As[kk + lc][mb + 8];
                af[t][2] = As[kk + lc + 4][mb];
                af[t][3] = As[kk + lc + 4][mb + 8];
            }
            #pragma unroll
            for (int u = 0; u < 4; u++) {
                int nb = warp_n * 32 + u * 8 + lr;
                bf[u][0] = Bs[kk + lc][nb];
                bf[u][1] = Bs[kk + lc + 4][nb];
            }
            #pragma unroll
            for (int t = 0; t < 4; t++)
                #pragma unroll
                for (int u = 0; u < 4; u++)
                    mma_tf32(c[t][u], af[t], bf[u][0], bf[u][1]);
        }
    }

    #pragma unroll
    for (int t = 0; t < 4; t++) {
        int row0 = m0 + warp_m * 64 + t * 16 + lr;
        #pragma unroll
        for (int u = 0; u < 4; u++) {
            int col0 = o0 + warp_n * 32 + u * 8 + lc * 2;
            #pragma unroll
            for (int e = 0; e < 4; e++) {
                int m = row0 + (e >> 1) * 8;
                int o = col0 + (e & 1);
                float val = c[t][u][e] + bias[o];
                if (mode <= 2) {
                    int tt = m >> 1, n = m & 1;
                    int h = o >> 6, dh = o & 63;
                    float* dst = (mode == 0) ? g_q : (mode == 1) ? g_k : g_v;
                    dst[(((size_t)(n * H_NUM + h)) * T_SEQ + tt) * DH + dh] = val;
                } else {
                    outp[(size_t)m * C_DIM + o] = val;
                }
            }
        }
    }
}

// ---------------------------------------------------------------------------
// TF32 tensor-core flash attention, BQ=64 x BK=64, 4 warps (16 q-rows each).
// Dynamic smem: Ks[64][68] | Vs[64][72] | Ps[64][68] (tf32 bits).
// Q staged through Ps once, then held in registers.
// ---------------------------------------------------------------------------
#define BQA 64
#define BKA 64
#define KS_ST 68   // ≡4 mod 32: K b-frag loads conflict-free
#define VS_ST 72   // ≡8 mod 32: V b-frag loads conflict-free
#define PS_ST 68
#define ATTN_SMEM ((64 * KS_ST + 64 * VS_ST + 64 * PS_ST) * 4)

extern __shared__ unsigned smem_u[];

__global__ __launch_bounds__(128, 3) void attn_tc(const int* __restrict__ key_length)
{
    unsigned* KsU = smem_u;
    unsigned* VsU = KsU + 64 * KS_ST;
    unsigned* PsU = VsU + 64 * VS_ST;

    const int i0 = blockIdx.x * BQA;
    const int h  = blockIdx.y;
    const int n  = blockIdx.z;
    const int tid = threadIdx.x;
    const int lane = tid & 31;
    const int w = tid >> 5;
    const int lr = lane >> 2;    // 0..7
    const int lc = lane & 3;     // 0..3
    const int keylen = key_length[n];

    const float* Qg = g_q + ((size_t)(n * H_NUM + h)) * T_SEQ * DH;
    const float* Kg = g_k + ((size_t)(n * H_NUM + h)) * T_SEQ * DH;
    const float* Vg = g_v + ((size_t)(n * H_NUM + h)) * T_SEQ * DH;

    // Stage Q (scaled -> tf32) into PsU, then pull A-frags into registers.
    {
        int r = tid >> 1;
        int cb = (tid & 1) * 32;
        const float* src = Qg + (size_t)(i0 + r) * DH + cb;
        unsigned* dst = PsU + r * PS_ST + cb;
        #pragma unroll
        for (int u = 0; u < 8; u++) {
            float4 v4 = *(const float4*)(src + u * 4);
            dst[u * 4 + 0] = f2tf32(v4.x * SCALE);
            dst[u * 4 + 1] = f2tf32(v4.y * SCALE);
            dst[u * 4 + 2] = f2tf32(v4.z * SCALE);
            dst[u * 4 + 3] = f2tf32(v4.w * SCALE);
        }
    }
    __syncthreads();

    const int rA = w * 16 + lr;      // this thread's row pair: rA, rA+8
    unsigned qf[8][4];
    #pragma unroll
    for (int kk = 0; kk < 8; kk++) {
        qf[kk][0] = PsU[rA * PS_ST + kk * 8 + lc];
        qf[kk][1] = PsU[(rA + 8) * PS_ST + kk * 8 + lc];
        qf[kk][2] = PsU[rA * PS_ST + kk * 8 + lc + 4];
        qf[kk][3] = PsU[(rA + 8) * PS_ST + kk * 8 + lc + 4];
    }

    float o[8][4];
    #pragma unroll
    for (int f = 0; f < 8; f++)
        #pragma unroll
        for (int e = 0; e < 4; e++) o[f][e] = 0.0f;
    float m0 = -1e30f, m1 = -1e30f, l0 = 0.0f, l1 = 0.0f;

    const int igA = i0 + w * 16 + lr;
    const int igB = igA + 8;

    for (int j0 = 0; j0 < T_SEQ; j0 += BKA) {
        bool needed = (j0 < keylen) ||
                      ((j0 + BKA - 1 >= i0 - WIN) && (j0 <= i0 + BQA - 1 + WIN));
        if (!needed) continue;

        __syncthreads();   // protect Ks/Vs (and first iter: Q staging reads done)
        {
            int r = tid >> 1;
            int cb = (tid & 1) * 32;
            const float* ks = Kg + (size_t)(j0 + r) * DH + cb;
            const float* vs = Vg + (size_t)(j0 + r) * DH + cb;
            unsigned* kd = KsU + r * KS_ST + cb;
            unsigned* vd = VsU + r * VS_ST + cb;
            #pragma unroll
            for (int u = 0; u < 8; u++) {
                float4 a = *(const float4*)(ks + u * 4);
                kd[u * 4 + 0] = f2tf32(a.x);
                kd[u * 4 + 1] = f2tf32(a.y);
                kd[u * 4 + 2] = f2tf32(a.z);
                kd[u * 4 + 3] = f2tf32(a.w);
                float4 b = *(const float4*)(vs + u * 4);
                vd[u * 4 + 0] = f2tf32(b.x);
                vd[u * 4 + 1] = f2tf32(b.y);
                vd[u * 4 + 2] = f2tf32(b.z);
                vd[u * 4 + 3] = f2tf32(b.w);
            }
        }
        __syncthreads();

        // S = Qscaled @ K^T   (8 n-frags of 8 keys each)
        float s[8][4];
        #pragma unroll
        for (int f = 0; f < 8; f++)
            #pragma unroll
            for (int e = 0; e < 4; e++) s[f][e] = 0.0f;
        #pragma unroll
        for (int kk = 0; kk < 8; kk++) {
            #pragma unroll
            for (int f = 0; f < 8; f++) {
                unsigned b0 = KsU[(f * 8 + lr) * KS_ST + kk * 8 + lc];
                unsigned b1 = KsU[(f * 8 + lr) * KS_ST + kk * 8 + lc + 4];
                mma_tf32(s[f], qf[kk], b0, b1);
            }
        }

        // Mask only boundary blocks
        bool fullok = (j0 + BKA - 1 < keylen) ||
                      (j0 >= i0 - 65 && j0 <= i0 + 65);
        if (!fullok) {
            #pragma unroll
            for (int f = 0; f < 8; f++) {
                int jg0 = j0 + f * 8 + 2 * lc;
                int jg1 = jg0 + 1;
                int dA0 = igA - jg0, dA1 = igA - jg1;
                int dB0 = igB - jg0, dB1 = igB - jg1;
                if (!(jg0 < keylen || (dA0 <= WIN && dA0 >= -WIN))) s[f][0] = -1e30f;
                if (!(jg1 < keylen || (dA1 <= WIN && dA1 >= -WIN))) s[f][1] = -1e30f;
                if (!(jg0 < keylen || (dB0 <= WIN && dB0 >= -WIN))) s[f][2] = -1e30f;
                if (!(jg1 < keylen || (dB1 <= WIN && dB1 >= -WIN))) s[f][3] = -1e30f;
            }
        }

        // Online softmax for the two rows this thread co-owns (quad-shuffle)
        float rmA = -1e30f, rmB = -1e30f;
        #pragma unroll
        for (int f = 0; f < 8; f++) {
            rmA = fmaxf(rmA, fmaxf(s[f][0], s[f][1]));
            rmB = fmaxf(rmB, fmaxf(s[f][2], s[f][3]));
        }
        rmA = fmaxf(rmA, __shfl_xor_sync(0xffffffffu, rmA, 1));
        rmA = fmaxf(rmA, __shfl_xor_sync(0xffffffffu, rmA, 2));
        rmB = fmaxf(rmB, __shfl_xor_sync(0xffffffffu, rmB, 1));
        rmB = fmaxf(rmB, __shfl_xor_sync(0xffffffffu, rmB, 2));

        float mn0 = fmaxf(m0, rmA);
        float mn1 = fmaxf(m1, rmB);
        float c0 = __expf(m0 - mn0);
        float c1 = __expf(m1 - mn1);

        __syncwarp();   // PsU reads (prev PV) done before overwriting
        float sa = 0.0f, sb = 0.0f;
        #pragma unroll
        for (int f = 0; f < 8; f++) {
            float p0 = __expf(s[f][0] - mn0);
            float p1 = __expf(s[f][1] - mn0);
            float p2 = __expf(s[f][2] - mn1);
            float p3 = __expf(s[f][3] - mn1);
            sa += p0 + p1;
            sb += p2 + p3;
            int cb = f * 8 + 2 * lc;
            PsU[rA * PS_ST + cb]           = f2tf32(p0);
            PsU[rA * PS_ST + cb + 1]       = f2tf32(p1);
            PsU[(rA + 8) * PS_ST + cb]     = f2tf32(p2);
            PsU[(rA + 8) * PS_ST + cb + 1] = f2tf32(p3);
            o[f][0] *= c0; o[f][1] *= c0;
            o[f][2] *= c1; o[f][3] *= c1;
        }
        sa += __shfl_xor_sync(0xffffffffu, sa, 1);
        sa += __shfl_xor_sync(0xffffffffu, sa, 2);
        sb += __shfl_xor_sync(0xffffffffu, sb, 1);
        sb += __shfl_xor_sync(0xffffffffu, sb, 2);
        l0 = l0 * c0 + sa;
        l1 = l1 * c1 + sb;
        m0 = mn0;
        m1 = mn1;
        __syncwarp();   // P visible to whole warp

        // O += P @ V
        #pragma unroll
        for (int kk = 0; kk < 8; kk++) {
            unsigned pa[4];
            pa[0] = PsU[rA * PS_ST + kk * 8 + lc];
            pa[1] = PsU[(rA + 8) * PS_ST + kk * 8 + lc];
            pa[2] = PsU[rA * PS_ST + kk * 8 + lc + 4];
            pa[3] = PsU[(rA + 8) * PS_ST + kk * 8 + lc + 4];
            #pragma unroll
            for (int f = 0; f < 8; f++) {
                unsigned b0 = VsU[(kk * 8 + lc) * VS_ST + f * 8 + lr];
                unsigned b1 = VsU[(kk * 8 + lc + 4) * VS_ST + f * 8 + lr];
                mma_tf32(o[f], pa, b0, b1);
            }
        }
    }

    // Normalize and write to g_y in (t, n, c) layout
    float inv0 = 1.0f / l0;
    float inv1 = 1.0f / l1;
    #pragma unroll
    for (int f = 0; f < 8; f++) {
        int col = h * DH + f * 8 + 2 * lc;
        float2 vA = make_float2(o[f][0] * inv0, o[f][1] * inv0);
        float2 vB = make_float2(o[f][2] * inv1, o[f][3] * inv1);
        *(float2*)&g_y[((size_t)igA * NB + n) * C_DIM + col] = vA;
        *(float2*)&g_y[((size_t)igB * NB + n) * C_DIM + col] = vB;
    }
}

// ---------------------------------------------------------------------------
extern "C" void kernel_launch(void* const* d_in, const int* in_sizes, int n_in,
                              void* d_out, int out_size)
{
    const float* q  = (const float*)d_in[0];
    const float* k  = (const float*)d_in[1];
    const float* v  = (const float*)d_in[2];
    const float* Wq = (const float*)d_in[3];
    const float* bq = (const float*)d_in[4];
    const float* Wk = (const float*)d_in[5];
    const float* bk = (const float*)d_in[6];
    const float* Wv = (const float*)d_in[7];
    const float* bv = (const float*)d_in[8];
    const float* Wo = (const float*)d_in[9];
    const float* bo = (const float*)d_in[10];
    const int* keylen = (const int*)d_in[11];

    // Idempotent, capture-safe host attribute set (no static guard).
    cudaFuncSetAttribute(attn_tc, cudaFuncAttributeMaxDynamicSharedMemorySize,
                         ATTN_SMEM);

    dim3 gg(M_ROWS / 128, C_DIM / 128);

    mma_gemm<<<gg, 256>>>(q, Wq, bq, nullptr, 0);
    mma_gemm<<<gg, 256>>>(k, Wk, bk, nullptr, 1);
    mma_gemm<<<gg, 256>>>(v, Wv, bv, nullptr, 2);

    attn_tc<<<dim3(T_SEQ / BQA, H_NUM, NB), 128, ATTN_SMEM>>>(keylen);

    mma_gemm<<<gg, 256>>>(nullptr, Wo, bo, (float*)d_out, 3);
}

// round 6
// speedup vs baseline: 1.9558x; 1.0446x over previous
#include <cuda_runtime.h>
#include <math.h>

// Problem constants (fixed shapes)
#define T_SEQ 2048
#define NB    2
#define C_DIM 1024
#define H_NUM 16
#define DH    64
#define M_ROWS (T_SEQ * NB)   // 4096
#define WIN   128
#define SCALE 0.125f          // 1/sqrt(64)

// Scratch: projected Q/K/V in (N, H, T, Dh) layout + attention output in (M, C)
__device__ float g_q[NB * H_NUM * T_SEQ * DH];
__device__ float g_k[NB * H_NUM * T_SEQ * DH];
__device__ float g_v[NB * H_NUM * T_SEQ * DH];
__device__ float g_y[M_ROWS * C_DIM];

__device__ __forceinline__ unsigned f2tf32(float x) {
    unsigned y;
    asm("cvt.rna.tf32.f32 %0, %1;" : "=r"(y) : "f"(x));
    return y;
}

__device__ __forceinline__ void mma_tf32(float* c, const unsigned* a,
                                         unsigned b0, unsigned b1) {
    asm volatile(
        "mma.sync.aligned.m16n8k8.row.col.f32.tf32.tf32.f32 "
        "{%0,%1,%2,%3}, {%4,%5,%6,%7}, {%8,%9}, {%0,%1,%2,%3};"
        : "+f"(c[0]), "+f"(c[1]), "+f"(c[2]), "+f"(c[3])
        : "r"(a[0]), "r"(a[1]), "r"(a[2]), "r"(a[3]), "r"(b0), "r"(b1));
}

// ---------------------------------------------------------------------------
// TF32 GEMM v2: out = X @ W^T + bias, double-buffered smem, [row][k] layout.
// Block tile 128x128, K staged 32; 8 warps as 2(M) x 4(N), warp tile 64x32.
// mode 0: z in {0,1,2} selects q/k/v projection, scatter to g_q/g_k/g_v.
// mode 1: X = g_y, W = Wo -> plain row-major (M, C) to outp.
// Dynamic smem: A[2][128][36] | B[2][128][36] (tf32 bits) = 73.7 KB.
// ---------------------------------------------------------------------------
#define GST 36
#define GEMM_SMEM (2 * 2 * 128 * GST * 4)

extern __shared__ unsigned dsm[];

__global__ __launch_bounds__(256, 2) void mma_gemm2(
    const float* __restrict__ xq, const float* __restrict__ xk,
    const float* __restrict__ xv,
    const float* __restrict__ Wq, const float* __restrict__ Wk,
    const float* __restrict__ Wv,
    const float* __restrict__ bq, const float* __restrict__ bk,
    const float* __restrict__ bv,
    const float* __restrict__ Wo, const float* __restrict__ bo,
    float* __restrict__ outp, int mode)
{
    unsigned* Ab[2] = {dsm, dsm + 128 * GST};
    unsigned* Bb[2] = {dsm + 2 * 128 * GST, dsm + 3 * 128 * GST};

    const int K = C_DIM;
    const int m0 = blockIdx.x * 128;
    const int o0 = blockIdx.y * 128;
    const int which = blockIdx.z;
    const int tid = threadIdx.x;
    const int lane = tid & 31;
    const int wid = tid >> 5;
    const int warp_m = wid & 1;
    const int warp_n = wid >> 1;
    const int lr = lane >> 2;
    const int lc = lane & 3;

    const float* X;
    const float* W;
    const float* bias;
    if (mode == 0) {
        X    = (which == 0) ? xq : (which == 1) ? xk : xv;
        W    = (which == 0) ? Wq : (which == 1) ? Wk : Wv;
        bias = (which == 0) ? bq : (which == 1) ? bk : bv;
    } else {
        X = g_y; W = Wo; bias = bo;
    }

    const int r  = tid >> 1;           // 0..127
    const int kb = (tid & 1) * 16;     // 0 or 16
    const float* Aptr = X + (size_t)(m0 + r) * K + kb;
    const float* Bptr = W + (size_t)(o0 + r) * K + kb;
    const int soff = r * GST + kb;

    float c[4][4][4];
    #pragma unroll
    for (int t = 0; t < 4; t++)
        #pragma unroll
        for (int u = 0; u < 4; u++)
            #pragma unroll
            for (int e = 0; e < 4; e++) c[t][u][e] = 0.0f;

    // Prologue: stage 0
    {
        #pragma unroll
        for (int u = 0; u < 4; u++) {
            float4 a = *(const float4*)(Aptr + u * 4);
            float4 b = *(const float4*)(Bptr + u * 4);
            uint4 ua = make_uint4(f2tf32(a.x), f2tf32(a.y), f2tf32(a.z), f2tf32(a.w));
            uint4 ub = make_uint4(f2tf32(b.x), f2tf32(b.y), f2tf32(b.z), f2tf32(b.w));
            *(uint4*)(Ab[0] + soff + u * 4) = ua;
            *(uint4*)(Bb[0] + soff + u * 4) = ub;
        }
    }
    __syncthreads();

    const int arow = warp_m * 64 + lr;        // + t*16
    const int brow = warp_n * 32 + lr;        // + u*8

    for (int s = 0; s < 32; s++) {
        const int cur = s & 1;
        const unsigned* Ac = Ab[cur];
        const unsigned* Bc = Bb[cur];
        unsigned* An = Ab[cur ^ 1];
        unsigned* Bn = Bb[cur ^ 1];
        const bool more = (s + 1 < 32);

        float4 ra[4];
        if (more) {
            #pragma unroll
            for (int u = 0; u < 4; u++)
                ra[u] = *(const float4*)(Aptr + (s + 1) * 32 + u * 4);
        }

        // kk = 0, 8
        #pragma unroll
        for (int kk = 0; kk < 16; kk += 8) {
            unsigned af[4][4], bf[4][2];
            #pragma unroll
            for (int t = 0; t < 4; t++) {
                int rr = (arow + t * 16) * GST + kk + lc;
                af[t][0] = Ac[rr];
                af[t][1] = Ac[rr + 8 * GST];
                af[t][2] = Ac[rr + 4];
                af[t][3] = Ac[rr + 8 * GST + 4];
            }
            #pragma unroll
            for (int u = 0; u < 4; u++) {
                int rr = (brow + u * 8) * GST + kk + lc;
                bf[u][0] = Bc[rr];
                bf[u][1] = Bc[rr + 4];
            }
            #pragma unroll
            for (int t = 0; t < 4; t++)
                #pragma unroll
                for (int u = 0; u < 4; u++)
                    mma_tf32(c[t][u], af[t], bf[u][0], bf[u][1]);
        }

        // Mid: store A(s+1), load B(s+1)
        float4 rb[4];
        if (more) {
            #pragma unroll
            for (int u = 0; u < 4; u++) {
                uint4 ua = make_uint4(f2tf32(ra[u].x), f2tf32(ra[u].y),
                                      f2tf32(ra[u].z), f2tf32(ra[u].w));
                *(uint4*)(An + soff + u * 4) = ua;
            }
            #pragma unroll
            for (int u = 0; u < 4; u++)
                rb[u] = *(const float4*)(Bptr + (s + 1) * 32 + u * 4);
        }

        // kk = 16, 24
        #pragma unroll
        for (int kk = 16; kk < 32; kk += 8) {
            unsigned af[4][4], bf[4][2];
            #pragma unroll
            for (int t = 0; t < 4; t++) {
                int rr = (arow + t * 16) * GST + kk + lc;
                af[t][0] = Ac[rr];
                af[t][1] = Ac[rr + 8 * GST];
                af[t][2] = Ac[rr + 4];
                af[t][3] = Ac[rr + 8 * GST + 4];
            }
            #pragma unroll
            for (int u = 0; u < 4; u++) {
                int rr = (brow + u * 8) * GST + kk + lc;
                bf[u][0] = Bc[rr];
                bf[u][1] = Bc[rr + 4];
            }
            #pragma unroll
            for (int t = 0; t < 4; t++)
                #pragma unroll
                for (int u = 0; u < 4; u++)
                    mma_tf32(c[t][u], af[t], bf[u][0], bf[u][1]);
        }

        if (more) {
            #pragma unroll
            for (int u = 0; u < 4; u++) {
                uint4 ub = make_uint4(f2tf32(rb[u].x), f2tf32(rb[u].y),
                                      f2tf32(rb[u].z), f2tf32(rb[u].w));
                *(uint4*)(Bn + soff + u * 4) = ub;
            }
        }
        __syncthreads();
    }

    // Epilogue: c[t][u]: rows {lr, lr+8}, cols {2*lc, 2*lc+1}
    #pragma unroll
    for (int t = 0; t < 4; t++) {
        int row0 = m0 + warp_m * 64 + t * 16 + lr;
        #pragma unroll
        for (int u = 0; u < 4; u++) {
            int col0 = o0 + warp_n * 32 + u * 8 + lc * 2;
            #pragma unroll
            for (int e = 0; e < 4; e++) {
                int m = row0 + (e >> 1) * 8;
                int o = col0 + (e & 1);
                float val = c[t][u][e] + bias[o];
                if (mode == 0) {
                    int tt = m >> 1, n = m & 1;
                    int h = o >> 6, dh = o & 63;
                    float* dst = (which == 0) ? g_q : (which == 1) ? g_k : g_v;
                    dst[(((size_t)(n * H_NUM + h)) * T_SEQ + tt) * DH + dh] = val;
                } else {
                    outp[(size_t)m * C_DIM + o] = val;
                }
            }
        }
    }
}

// ---------------------------------------------------------------------------
// TF32 tensor-core flash attention, BQ=64 x BK=64, 4 warps (16 q-rows each).
// (unchanged from round 5 — measured 209.6 us)
// ---------------------------------------------------------------------------
#define BQA 64
#define BKA 64
#define KS_ST 68
#define VS_ST 72
#define PS_ST 68
#define ATTN_SMEM ((64 * KS_ST + 64 * VS_ST + 64 * PS_ST) * 4)

__global__ __launch_bounds__(128, 3) void attn_tc(const int* __restrict__ key_length)
{
    unsigned* KsU = dsm;
    unsigned* VsU = KsU + 64 * KS_ST;
    unsigned* PsU = VsU + 64 * VS_ST;

    const int i0 = blockIdx.x * BQA;
    const int h  = blockIdx.y;
    const int n  = blockIdx.z;
    const int tid = threadIdx.x;
    const int lane = tid & 31;
    const int w = tid >> 5;
    const int lr = lane >> 2;
    const int lc = lane & 3;
    const int keylen = key_length[n];

    const float* Qg = g_q + ((size_t)(n * H_NUM + h)) * T_SEQ * DH;
    const float* Kg = g_k + ((size_t)(n * H_NUM + h)) * T_SEQ * DH;
    const float* Vg = g_v + ((size_t)(n * H_NUM + h)) * T_SEQ * DH;

    {
        int r = tid >> 1;
        int cb = (tid & 1) * 32;
        const float* src = Qg + (size_t)(i0 + r) * DH + cb;
        unsigned* dst = PsU + r * PS_ST + cb;
        #pragma unroll
        for (int u = 0; u < 8; u++) {
            float4 v4 = *(const float4*)(src + u * 4);
            dst[u * 4 + 0] = f2tf32(v4.x * SCALE);
            dst[u * 4 + 1] = f2tf32(v4.y * SCALE);
            dst[u * 4 + 2] = f2tf32(v4.z * SCALE);
            dst[u * 4 + 3] = f2tf32(v4.w * SCALE);
        }
    }
    __syncthreads();

    const int rA = w * 16 + lr;
    unsigned qf[8][4];
    #pragma unroll
    for (int kk = 0; kk < 8; kk++) {
        qf[kk][0] = PsU[rA * PS_ST + kk * 8 + lc];
        qf[kk][1] = PsU[(rA + 8) * PS_ST + kk * 8 + lc];
        qf[kk][2] = PsU[rA * PS_ST + kk * 8 + lc + 4];
        qf[kk][3] = PsU[(rA + 8) * PS_ST + kk * 8 + lc + 4];
    }

    float o[8][4];
    #pragma unroll
    for (int f = 0; f < 8; f++)
        #pragma unroll
        for (int e = 0; e < 4; e++) o[f][e] = 0.0f;
    float m0 = -1e30f, m1 = -1e30f, l0 = 0.0f, l1 = 0.0f;

    const int igA = i0 + w * 16 + lr;
    const int igB = igA + 8;

    for (int j0 = 0; j0 < T_SEQ; j0 += BKA) {
        bool needed = (j0 < keylen) ||
                      ((j0 + BKA - 1 >= i0 - WIN) && (j0 <= i0 + BQA - 1 + WIN));
        if (!needed) continue;

        __syncthreads();
        {
            int r = tid >> 1;
            int cb = (tid & 1) * 32;
            const float* ks = Kg + (size_t)(j0 + r) * DH + cb;
            const float* vs = Vg + (size_t)(j0 + r) * DH + cb;
            unsigned* kd = KsU + r * KS_ST + cb;
            unsigned* vd = VsU + r * VS_ST + cb;
            #pragma unroll
            for (int u = 0; u < 8; u++) {
                float4 a = *(const float4*)(ks + u * 4);
                kd[u * 4 + 0] = f2tf32(a.x);
                kd[u * 4 + 1] = f2tf32(a.y);
                kd[u * 4 + 2] = f2tf32(a.z);
                kd[u * 4 + 3] = f2tf32(a.w);
                float4 b = *(const float4*)(vs + u * 4);
                vd[u * 4 + 0] = f2tf32(b.x);
                vd[u * 4 + 1] = f2tf32(b.y);
                vd[u * 4 + 2] = f2tf32(b.z);
                vd[u * 4 + 3] = f2tf32(b.w);
            }
        }
        __syncthreads();

        float s[8][4];
        #pragma unroll
        for (int f = 0; f < 8; f++)
            #pragma unroll
            for (int e = 0; e < 4; e++) s[f][e] = 0.0f;
        #pragma unroll
        for (int kk = 0; kk < 8; kk++) {
            #pragma unroll
            for (int f = 0; f < 8; f++) {
                unsigned b0 = KsU[(f * 8 + lr) * KS_ST + kk * 8 + lc];
                unsigned b1 = KsU[(f * 8 + lr) * KS_ST + kk * 8 + lc + 4];
                mma_tf32(s[f], qf[kk], b0, b1);
            }
        }

        bool fullok = (j0 + BKA - 1 < keylen) ||
                      (j0 >= i0 - 65 && j0 <= i0 + 65);
        if (!fullok) {
            #pragma unroll
            for (int f = 0; f < 8; f++) {
                int jg0 = j0 + f * 8 + 2 * lc;
                int jg1 = jg0 + 1;
                int dA0 = igA - jg0, dA1 = igA - jg1;
                int dB0 = igB - jg0, dB1 = igB - jg1;
                if (!(jg0 < keylen || (dA0 <= WIN && dA0 >= -WIN))) s[f][0] = -1e30f;
                if (!(jg1 < keylen || (dA1 <= WIN && dA1 >= -WIN))) s[f][1] = -1e30f;
                if (!(jg0 < keylen || (dB0 <= WIN && dB0 >= -WIN))) s[f][2] = -1e30f;
                if (!(jg1 < keylen || (dB1 <= WIN && dB1 >= -WIN))) s[f][3] = -1e30f;
            }
        }

        float rmA = -1e30f, rmB = -1e30f;
        #pragma unroll
        for (int f = 0; f < 8; f++) {
            rmA = fmaxf(rmA, fmaxf(s[f][0], s[f][1]));
            rmB = fmaxf(rmB, fmaxf(s[f][2], s[f][3]));
        }
        rmA = fmaxf(rmA, __shfl_xor_sync(0xffffffffu, rmA, 1));
        rmA = fmaxf(rmA, __shfl_xor_sync(0xffffffffu, rmA, 2));
        rmB = fmaxf(rmB, __shfl_xor_sync(0xffffffffu, rmB, 1));
        rmB = fmaxf(rmB, __shfl_xor_sync(0xffffffffu, rmB, 2));

        float mn0 = fmaxf(m0, rmA);
        float mn1 = fmaxf(m1, rmB);
        float c0 = __expf(m0 - mn0);
        float c1 = __expf(m1 - mn1);

        __syncwarp();
        float sa = 0.0f, sb = 0.0f;
        #pragma unroll
        for (int f = 0; f < 8; f++) {
            float p0 = __expf(s[f][0] - mn0);
            float p1 = __expf(s[f][1] - mn0);
            float p2 = __expf(s[f][2] - mn1);
            float p3 = __expf(s[f][3] - mn1);
            sa += p0 + p1;
            sb += p2 + p3;
            int cb = f * 8 + 2 * lc;
            PsU[rA * PS_ST + cb]           = f2tf32(p0);
            PsU[rA * PS_ST + cb + 1]       = f2tf32(p1);
            PsU[(rA + 8) * PS_ST + cb]     = f2tf32(p2);
            PsU[(rA + 8) * PS_ST + cb + 1] = f2tf32(p3);
            o[f][0] *= c0; o[f][1] *= c0;
            o[f][2] *= c1; o[f][3] *= c1;
        }
        sa += __shfl_xor_sync(0xffffffffu, sa, 1);
        sa += __shfl_xor_sync(0xffffffffu, sa, 2);
        sb += __shfl_xor_sync(0xffffffffu, sb, 1);
        sb += __shfl_xor_sync(0xffffffffu, sb, 2);
        l0 = l0 * c0 + sa;
        l1 = l1 * c1 + sb;
        m0 = mn0;
        m1 = mn1;
        __syncwarp();

        #pragma unroll
        for (int kk = 0; kk < 8; kk++) {
            unsigned pa[4];
            pa[0] = PsU[rA * PS_ST + kk * 8 + lc];
            pa[1] = PsU[(rA + 8) * PS_ST + kk * 8 + lc];
            pa[2] = PsU[rA * PS_ST + kk * 8 + lc + 4];
            pa[3] = PsU[(rA + 8) * PS_ST + kk * 8 + lc + 4];
            #pragma unroll
            for (int f = 0; f < 8; f++) {
                unsigned b0 = VsU[(kk * 8 + lc) * VS_ST + f * 8 + lr];
                unsigned b1 = VsU[(kk * 8 + lc + 4) * VS_ST + f * 8 + lr];
                mma_tf32(o[f], pa, b0, b1);
            }
        }
    }

    float inv0 = 1.0f / l0;
    float inv1 = 1.0f / l1;
    #pragma unroll
    for (int f = 0; f < 8; f++) {
        int col = h * DH + f * 8 + 2 * lc;
        float2 vA = make_float2(o[f][0] * inv0, o[f][1] * inv0);
        float2 vB = make_float2(o[f][2] * inv1, o[f][3] * inv1);
        *(float2*)&g_y[((size_t)igA * NB + n) * C_DIM + col] = vA;
        *(float2*)&g_y[((size_t)igB * NB + n) * C_DIM + col] = vB;
    }
}

// ---------------------------------------------------------------------------
extern "C" void kernel_launch(void* const* d_in, const int* in_sizes, int n_in,
                              void* d_out, int out_size)
{
    const float* q  = (const float*)d_in[0];
    const float* k  = (const float*)d_in[1];
    const float* v  = (const float*)d_in[2];
    const float* Wq = (const float*)d_in[3];
    const float* bq = (const float*)d_in[4];
    const float* Wk = (const float*)d_in[5];
    const float* bk = (const float*)d_in[6];
    const float* Wv = (const float*)d_in[7];
    const float* bv = (const float*)d_in[8];
    const float* Wo = (const float*)d_in[9];
    const float* bo = (const float*)d_in[10];
    const int* keylen = (const int*)d_in[11];

    cudaFuncSetAttribute(mma_gemm2, cudaFuncAttributeMaxDynamicSharedMemorySize,
                         GEMM_SMEM);
    cudaFuncSetAttribute(attn_tc, cudaFuncAttributeMaxDynamicSharedMemorySize,
                         ATTN_SMEM);

    // Fused Q/K/V projections (z = 0,1,2)
    mma_gemm2<<<dim3(M_ROWS / 128, C_DIM / 128, 3), 256, GEMM_SMEM>>>(
        q, k, v, Wq, Wk, Wv, bq, bk, bv, Wo, bo, nullptr, 0);

    attn_tc<<<dim3(T_SEQ / BQA, H_NUM, NB), 128, ATTN_SMEM>>>(keylen);

    // Output projection
    mma_gemm2<<<dim3(M_ROWS / 128, C_DIM / 128, 1), 256, GEMM_SMEM>>>(
        q, k, v, Wq, Wk, Wv, bq, bk, bv, Wo, bo, (float*)d_out, 1);
}

// round 7
// speedup vs baseline: 2.3794x; 1.2166x over previous
#include <cuda_runtime.h>
#include <math.h>

// Problem constants (fixed shapes)
#define T_SEQ 2048
#define NB    2
#define C_DIM 1024
#define H_NUM 16
#define DH    64
#define M_ROWS (T_SEQ * NB)   // 4096
#define WIN   128
#define SCALE 0.125f          // 1/sqrt(64)

// Scratch: projected Q/K/V in (N, H, T, Dh) layout + attention output in (M, C)
__device__ float g_q[NB * H_NUM * T_SEQ * DH];
__device__ float g_k[NB * H_NUM * T_SEQ * DH];
__device__ float g_v[NB * H_NUM * T_SEQ * DH];
__device__ float g_y[M_ROWS * C_DIM];

__device__ __forceinline__ unsigned f2tf32(float x) {
    unsigned y;
    asm("cvt.rna.tf32.f32 %0, %1;" : "=r"(y) : "f"(x));
    return y;
}

__device__ __forceinline__ void mma_tf32(float* c, const unsigned* a,
                                         unsigned b0, unsigned b1) {
    asm volatile(
        "mma.sync.aligned.m16n8k8.row.col.f32.tf32.tf32.f32 "
        "{%0,%1,%2,%3}, {%4,%5,%6,%7}, {%8,%9}, {%0,%1,%2,%3};"
        : "+f"(c[0]), "+f"(c[1]), "+f"(c[2]), "+f"(c[3])
        : "r"(a[0]), "r"(a[1]), "r"(a[2]), "r"(a[3]), "r"(b0), "r"(b1));
}

// ldmatrix x4: four 8x8(b16) tiles = four tf32 fragment registers.
__device__ __forceinline__ void ldsm_x4(unsigned* r, unsigned addr) {
    asm volatile(
        "ldmatrix.sync.aligned.m8n8.x4.shared.b16 {%0,%1,%2,%3}, [%4];"
        : "=r"(r[0]), "=r"(r[1]), "=r"(r[2]), "=r"(r[3]) : "r"(addr));
}

// ---------------------------------------------------------------------------
// TF32 GEMM v3: double-buffered smem [row][k] (stride 36), ldmatrix frag loads.
// Block tile 128x128, K staged 32; 8 warps as 2(M) x 4(N), warp tile 64x32.
// mode 0: z in {0,1,2} selects q/k/v projection, scatter to g_q/g_k/g_v.
// mode 1: X = g_y, W = Wo -> plain row-major (M, C) to outp.
// ---------------------------------------------------------------------------
#define GST 36
#define GEMM_SMEM (2 * 2 * 128 * GST * 4)

extern __shared__ unsigned dsm[];

__global__ __launch_bounds__(256, 2) void mma_gemm2(
    const float* __restrict__ xq, const float* __restrict__ xk,
    const float* __restrict__ xv,
    const float* __restrict__ Wq, const float* __restrict__ Wk,
    const float* __restrict__ Wv,
    const float* __restrict__ bq, const float* __restrict__ bk,
    const float* __restrict__ bv,
    const float* __restrict__ Wo, const float* __restrict__ bo,
    float* __restrict__ outp, int mode)
{
    unsigned* Ab[2] = {dsm, dsm + 128 * GST};
    unsigned* Bb[2] = {dsm + 2 * 128 * GST, dsm + 3 * 128 * GST};

    const unsigned smem_u32 = (unsigned)__cvta_generic_to_shared(dsm);
    const unsigned Acv[2] = {smem_u32, smem_u32 + 128 * GST * 4};
    const unsigned Bcv[2] = {smem_u32 + 2 * 128 * GST * 4,
                             smem_u32 + 3 * 128 * GST * 4};

    const int K = C_DIM;
    const int m0 = blockIdx.x * 128;
    const int o0 = blockIdx.y * 128;
    const int which = blockIdx.z;
    const int tid = threadIdx.x;
    const int lane = tid & 31;
    const int wid = tid >> 5;
    const int warp_m = wid & 1;
    const int warp_n = wid >> 1;
    const int lr = lane >> 2;
    const int lc = lane & 3;

    const float* X;
    const float* W;
    const float* bias;
    if (mode == 0) {
        X    = (which == 0) ? xq : (which == 1) ? xk : xv;
        W    = (which == 0) ? Wq : (which == 1) ? Wk : Wv;
        bias = (which == 0) ? bq : (which == 1) ? bk : bv;
    } else {
        X = g_y; W = Wo; bias = bo;
    }

    const int r  = tid >> 1;           // 0..127
    const int kb = (tid & 1) * 16;     // 0 or 16
    const float* Aptr = X + (size_t)(m0 + r) * K + kb;
    const float* Bptr = W + (size_t)(o0 + r) * K + kb;
    const int soff = r * GST + kb;

    // Per-thread ldmatrix address components (word offsets)
    // A tiles (t,kk): order a0..a3 = (m0-7,k0-3),(m8-15,k0-3),(m0-7,k4-7),(m8-15,k4-7)
    const int a_m_add = ((lane >> 3) & 1) * 8 + (lane & 7);
    const int a_k_add = (lane >> 4) * 4;
    const int aoff = (warp_m * 64 + a_m_add) * GST + a_k_add;
    // B tiles (upair,kk): order = (n_u,k0-3),(n_u,k4-7),(n_u+1,k0-3),(n_u+1,k4-7)
    const int b_n_add = (lane & 7) + ((lane >> 4) * 8);
    const int b_k_add = ((lane >> 3) & 1) * 4;
    const int boff = (warp_n * 32 + b_n_add) * GST + b_k_add;

    float c[4][4][4];
    #pragma unroll
    for (int t = 0; t < 4; t++)
        #pragma unroll
        for (int u = 0; u < 4; u++)
            #pragma unroll
            for (int e = 0; e < 4; e++) c[t][u][e] = 0.0f;

    // Prologue: stage 0
    {
        #pragma unroll
        for (int u = 0; u < 4; u++) {
            float4 a = *(const float4*)(Aptr + u * 4);
            float4 b = *(const float4*)(Bptr + u * 4);
            uint4 ua = make_uint4(f2tf32(a.x), f2tf32(a.y), f2tf32(a.z), f2tf32(a.w));
            uint4 ub = make_uint4(f2tf32(b.x), f2tf32(b.y), f2tf32(b.z), f2tf32(b.w));
            *(uint4*)(Ab[0] + soff + u * 4) = ua;
            *(uint4*)(Bb[0] + soff + u * 4) = ub;
        }
    }
    __syncthreads();

    for (int s = 0; s < 32; s++) {
        const int cur = s & 1;
        const unsigned Ac = Acv[cur];
        const unsigned Bc = Bcv[cur];
        unsigned* An = Ab[cur ^ 1];
        unsigned* Bn = Bb[cur ^ 1];
        const bool more = (s + 1 < 32);

        float4 ra[4];
        if (more) {
            #pragma unroll
            for (int u = 0; u < 4; u++)
                ra[u] = *(const float4*)(Aptr + (s + 1) * 32 + u * 4);
        }

        // kk = 0, 8
        #pragma unroll
        for (int kk = 0; kk < 16; kk += 8) {
            unsigned af[4][4], bf[4][2];
            #pragma unroll
            for (int t = 0; t < 4; t++)
                ldsm_x4(af[t], Ac + 4u * (aoff + t * 16 * GST + kk));
            #pragma unroll
            for (int up = 0; up < 2; up++) {
                unsigned tmp[4];
                ldsm_x4(tmp, Bc + 4u * (boff + up * 16 * GST + kk));
                bf[2 * up][0] = tmp[0]; bf[2 * up][1] = tmp[1];
                bf[2 * up + 1][0] = tmp[2]; bf[2 * up + 1][1] = tmp[3];
            }
            #pragma unroll
            for (int t = 0; t < 4; t++)
                #pragma unroll
                for (int u = 0; u < 4; u++)
                    mma_tf32(c[t][u], af[t], bf[u][0], bf[u][1]);
        }

        // Mid: store A(s+1), load B(s+1)
        float4 rb[4];
        if (more) {
            #pragma unroll
            for (int u = 0; u < 4; u++) {
                uint4 ua = make_uint4(f2tf32(ra[u].x), f2tf32(ra[u].y),
                                      f2tf32(ra[u].z), f2tf32(ra[u].w));
                *(uint4*)(An + soff + u * 4) = ua;
            }
            #pragma unroll
            for (int u = 0; u < 4; u++)
                rb[u] = *(const float4*)(Bptr + (s + 1) * 32 + u * 4);
        }

        // kk = 16, 24
        #pragma unroll
        for (int kk = 16; kk < 32; kk += 8) {
            unsigned af[4][4], bf[4][2];
            #pragma unroll
            for (int t = 0; t < 4; t++)
                ldsm_x4(af[t], Ac + 4u * (aoff + t * 16 * GST + kk));
            #pragma unroll
            for (int up = 0; up < 2; up++) {
                unsigned tmp[4];
                ldsm_x4(tmp, Bc + 4u * (boff + up * 16 * GST + kk));
                bf[2 * up][0] = tmp[0]; bf[2 * up][1] = tmp[1];
                bf[2 * up + 1][0] = tmp[2]; bf[2 * up + 1][1] = tmp[3];
            }
            #pragma unroll
            for (int t = 0; t < 4; t++)
                #pragma unroll
                for (int u = 0; u < 4; u++)
                    mma_tf32(c[t][u], af[t], bf[u][0], bf[u][1]);
        }

        if (more) {
            #pragma unroll
            for (int u = 0; u < 4; u++) {
                uint4 ub = make_uint4(f2tf32(rb[u].x), f2tf32(rb[u].y),
                                      f2tf32(rb[u].z), f2tf32(rb[u].w));
                *(uint4*)(Bn + soff + u * 4) = ub;
            }
        }
        __syncthreads();
    }

    // Epilogue: c[t][u]: rows {lr, lr+8}, cols {2*lc, 2*lc+1}
    #pragma unroll
    for (int t = 0; t < 4; t++) {
        int row0 = m0 + warp_m * 64 + t * 16 + lr;
        #pragma unroll
        for (int u = 0; u < 4; u++) {
            int col0 = o0 + warp_n * 32 + u * 8 + lc * 2;
            #pragma unroll
            for (int e = 0; e < 4; e++) {
                int m = row0 + (e >> 1) * 8;
                int o = col0 + (e & 1);
                float val = c[t][u][e] + bias[o];
                if (mode == 0) {
                    int tt = m >> 1, n = m & 1;
                    int h = o >> 6, dh = o & 63;
                    float* dst = (which == 0) ? g_q : (which == 1) ? g_k : g_v;
                    dst[(((size_t)(n * H_NUM + h)) * T_SEQ + tt) * DH + dh] = val;
                } else {
                    outp[(size_t)m * C_DIM + o] = val;
                }
            }
        }
    }
}

// ---------------------------------------------------------------------------
// TF32 tensor-core flash attention, BQ=64 x BK=64, 4 warps (16 q-rows each).
// (unchanged — measured 209.6 us)
// ---------------------------------------------------------------------------
#define BQA 64
#define BKA 64
#define KS_ST 68
#define VS_ST 72
#define PS_ST 68
#define ATTN_SMEM ((64 * KS_ST + 64 * VS_ST + 64 * PS_ST) * 4)

__global__ __launch_bounds__(128, 3) void attn_tc(const int* __restrict__ key_length)
{
    unsigned* KsU = dsm;
    unsigned* VsU = KsU + 64 * KS_ST;
    unsigned* PsU = VsU + 64 * VS_ST;

    const int i0 = blockIdx.x * BQA;
    const int h  = blockIdx.y;
    const int n  = blockIdx.z;
    const int tid = threadIdx.x;
    const int lane = tid & 31;
    const int w = tid >> 5;
    const int lr = lane >> 2;
    const int lc = lane & 3;
    const int keylen = key_length[n];

    const float* Qg = g_q + ((size_t)(n * H_NUM + h)) * T_SEQ * DH;
    const float* Kg = g_k + ((size_t)(n * H_NUM + h)) * T_SEQ * DH;
    const float* Vg = g_v + ((size_t)(n * H_NUM + h)) * T_SEQ * DH;

    {
        int r = tid >> 1;
        int cb = (tid & 1) * 32;
        const float* src = Qg + (size_t)(i0 + r) * DH + cb;
        unsigned* dst = PsU + r * PS_ST + cb;
        #pragma unroll
        for (int u = 0; u < 8; u++) {
            float4 v4 = *(const float4*)(src + u * 4);
            dst[u * 4 + 0] = f2tf32(v4.x * SCALE);
            dst[u * 4 + 1] = f2tf32(v4.y * SCALE);
            dst[u * 4 + 2] = f2tf32(v4.z * SCALE);
            dst[u * 4 + 3] = f2tf32(v4.w * SCALE);
        }
    }
    __syncthreads();

    const int rA = w * 16 + lr;
    unsigned qf[8][4];
    #pragma unroll
    for (int kk = 0; kk < 8; kk++) {
        qf[kk][0] = PsU[rA * PS_ST + kk * 8 + lc];
        qf[kk][1] = PsU[(rA + 8) * PS_ST + kk * 8 + lc];
        qf[kk][2] = PsU[rA * PS_ST + kk * 8 + lc + 4];
        qf[kk][3] = PsU[(rA + 8) * PS_ST + kk * 8 + lc + 4];
    }

    float o[8][4];
    #pragma unroll
    for (int f = 0; f < 8; f++)
        #pragma unroll
        for (int e = 0; e < 4; e++) o[f][e] = 0.0f;
    float m0 = -1e30f, m1 = -1e30f, l0 = 0.0f, l1 = 0.0f;

    const int igA = i0 + w * 16 + lr;
    const int igB = igA + 8;

    for (int j0 = 0; j0 < T_SEQ; j0 += BKA) {
        bool needed = (j0 < keylen) ||
                      ((j0 + BKA - 1 >= i0 - WIN) && (j0 <= i0 + BQA - 1 + WIN));
        if (!needed) continue;

        __syncthreads();
        {
            int r = tid >> 1;
            int cb = (tid & 1) * 32;
            const float* ks = Kg + (size_t)(j0 + r) * DH + cb;
            const float* vs = Vg + (size_t)(j0 + r) * DH + cb;
            unsigned* kd = KsU + r * KS_ST + cb;
            unsigned* vd = VsU + r * VS_ST + cb;
            #pragma unroll
            for (int u = 0; u < 8; u++) {
                float4 a = *(const float4*)(ks + u * 4);
                kd[u * 4 + 0] = f2tf32(a.x);
                kd[u * 4 + 1] = f2tf32(a.y);
                kd[u * 4 + 2] = f2tf32(a.z);
                kd[u * 4 + 3] = f2tf32(a.w);
                float4 b = *(const float4*)(vs + u * 4);
                vd[u * 4 + 0] = f2tf32(b.x);
                vd[u * 4 + 1] = f2tf32(b.y);
                vd[u * 4 + 2] = f2tf32(b.z);
                vd[u * 4 + 3] = f2tf32(b.w);
            }
        }
        __syncthreads();

        float s[8][4];
        #pragma unroll
        for (int f = 0; f < 8; f++)
            #pragma unroll
            for (int e = 0; e < 4; e++) s[f][e] = 0.0f;
        #pragma unroll
        for (int kk = 0; kk < 8; kk++) {
            #pragma unroll
            for (int f = 0; f < 8; f++) {
                unsigned b0 = KsU[(f * 8 + lr) * KS_ST + kk * 8 + lc];
                unsigned b1 = KsU[(f * 8 + lr) * KS_ST + kk * 8 + lc + 4];
                mma_tf32(s[f], qf[kk], b0, b1);
            }
        }

        bool fullok = (j0 + BKA - 1 < keylen) ||
                      (j0 >= i0 - 65 && j0 <= i0 + 65);
        if (!fullok) {
            #pragma unroll
            for (int f = 0; f < 8; f++) {
                int jg0 = j0 + f * 8 + 2 * lc;
                int jg1 = jg0 + 1;
                int dA0 = igA - jg0, dA1 = igA - jg1;
                int dB0 = igB - jg0, dB1 = igB - jg1;
                if (!(jg0 < keylen || (dA0 <= WIN && dA0 >= -WIN))) s[f][0] = -1e30f;
                if (!(jg1 < keylen || (dA1 <= WIN && dA1 >= -WIN))) s[f][1] = -1e30f;
                if (!(jg0 < keylen || (dB0 <= WIN && dB0 >= -WIN))) s[f][2] = -1e30f;
                if (!(jg1 < keylen || (dB1 <= WIN && dB1 >= -WIN))) s[f][3] = -1e30f;
            }
        }

        float rmA = -1e30f, rmB = -1e30f;
        #pragma unroll
        for (int f = 0; f < 8; f++) {
            rmA = fmaxf(rmA, fmaxf(s[f][0], s[f][1]));
            rmB = fmaxf(rmB, fmaxf(s[f][2], s[f][3]));
        }
        rmA = fmaxf(rmA, __shfl_xor_sync(0xffffffffu, rmA, 1));
        rmA = fmaxf(rmA, __shfl_xor_sync(0xffffffffu, rmA, 2));
        rmB = fmaxf(rmB, __shfl_xor_sync(0xffffffffu, rmB, 1));
        rmB = fmaxf(rmB, __shfl_xor_sync(0xffffffffu, rmB, 2));

        float mn0 = fmaxf(m0, rmA);
        float mn1 = fmaxf(m1, rmB);
        float c0 = __expf(m0 - mn0);
        float c1 = __expf(m1 - mn1);

        __syncwarp();
        float sa = 0.0f, sb = 0.0f;
        #pragma unroll
        for (int f = 0; f < 8; f++) {
            float p0 = __expf(s[f][0] - mn0);
            float p1 = __expf(s[f][1] - mn0);
            float p2 = __expf(s[f][2] - mn1);
            float p3 = __expf(s[f][3] - mn1);
            sa += p0 + p1;
            sb += p2 + p3;
            int cb = f * 8 + 2 * lc;
            PsU[rA * PS_ST + cb]           = f2tf32(p0);
            PsU[rA * PS_ST + cb + 1]       = f2tf32(p1);
            PsU[(rA + 8) * PS_ST + cb]     = f2tf32(p2);
            PsU[(rA + 8) * PS_ST + cb + 1] = f2tf32(p3);
            o[f][0] *= c0; o[f][1] *= c0;
            o[f][2] *= c1; o[f][3] *= c1;
        }
        sa += __shfl_xor_sync(0xffffffffu, sa, 1);
        sa += __shfl_xor_sync(0xffffffffu, sa, 2);
        sb += __shfl_xor_sync(0xffffffffu, sb, 1);
        sb += __shfl_xor_sync(0xffffffffu, sb, 2);
        l0 = l0 * c0 + sa;
        l1 = l1 * c1 + sb;
        m0 = mn0;
        m1 = mn1;
        __syncwarp();

        #pragma unroll
        for (int kk = 0; kk < 8; kk++) {
            unsigned pa[4];
            pa[0] = PsU[rA * PS_ST + kk * 8 + lc];
            pa[1] = PsU[(rA + 8) * PS_ST + kk * 8 + lc];
            pa[2] = PsU[rA * PS_ST + kk * 8 + lc + 4];
            pa[3] = PsU[(rA + 8) * PS_ST + kk * 8 + lc + 4];
            #pragma unroll
            for (int f = 0; f < 8; f++) {
                unsigned b0 = VsU[(kk * 8 + lc) * VS_ST + f * 8 + lr];
                unsigned b1 = VsU[(kk * 8 + lc + 4) * VS_ST + f * 8 + lr];
                mma_tf32(o[f], pa, b0, b1);
            }
        }
    }

    float inv0 = 1.0f / l0;
    float inv1 = 1.0f / l1;
    #pragma unroll
    for (int f = 0; f < 8; f++) {
        int col = h * DH + f * 8 + 2 * lc;
        float2 vA = make_float2(o[f][0] * inv0, o[f][1] * inv0);
        float2 vB = make_float2(o[f][2] * inv1, o[f][3] * inv1);
        *(float2*)&g_y[((size_t)igA * NB + n) * C_DIM + col] = vA;
        *(float2*)&g_y[((size_t)igB * NB + n) * C_DIM + col] = vB;
    }
}

// ---------------------------------------------------------------------------
extern "C" void kernel_launch(void* const* d_in, const int* in_sizes, int n_in,
                              void* d_out, int out_size)
{
    const float* q  = (const float*)d_in[0];
    const float* k  = (const float*)d_in[1];
    const float* v  = (const float*)d_in[2];
    const float* Wq = (const float*)d_in[3];
    const float* bq = (const float*)d_in[4];
    const float* Wk = (const float*)d_in[5];
    const float* bk = (const float*)d_in[6];
    const float* Wv = (const float*)d_in[7];
    const float* bv = (const float*)d_in[8];
    const float* Wo = (const float*)d_in[9];
    const float* bo = (const float*)d_in[10];
    const int* keylen = (const int*)d_in[11];

    cudaFuncSetAttribute(mma_gemm2, cudaFuncAttributeMaxDynamicSharedMemorySize,
                         GEMM_SMEM);
    cudaFuncSetAttribute(attn_tc, cudaFuncAttributeMaxDynamicSharedMemorySize,
                         ATTN_SMEM);

    // Fused Q/K/V projections (z = 0,1,2)
    mma_gemm2<<<dim3(M_ROWS / 128, C_DIM / 128, 3), 256, GEMM_SMEM>>>(
        q, k, v, Wq, Wk, Wv, bq, bk, bv, Wo, bo, nullptr, 0);

    attn_tc<<<dim3(T_SEQ / BQA, H_NUM, NB), 128, ATTN_SMEM>>>(keylen);

    // Output projection
    mma_gemm2<<<dim3(M_ROWS / 128, C_DIM / 128, 1), 256, GEMM_SMEM>>>(
        q, k, v, Wq, Wk, Wv, bq, bk, bv, Wo, bo, (float*)d_out, 1);
}